// round 17
// baseline (speedup 1.0000x reference)
#include <cuda_runtime.h>
#include <cuda_fp16.h>
#include <cstdint>
#include <math.h>

#define EMBED 4096
#define NH 16
#define HD 256
#define NB 2
#define NS 2048
#define NTOK (NB * NS)
#define NELEM ((size_t)NTOK * EMBED)

__device__ __half g_hs_h[NELEM];
__device__ __half g_wq_h[NELEM];
__device__ __half g_wk_h[NELEM];
__device__ __half g_wv_h[NELEM];
__device__ __half g_wo_h[NELEM];
__device__ __half g_qh[NELEM];
__device__ __half g_kh[NELEM];
__device__ __half g_v[NELEM];
__device__ __half g_att[NELEM];

// ---------------- PTX helpers (baseline ISA; tcgen05 is sm_103a-gated) ------
__device__ __forceinline__ uint32_t smem_u32(const void* p) {
    uint32_t a;
    asm("{ .reg .u64 t; cvta.to.shared.u64 t, %1; cvt.u32.u64 %0, t; }"
        : "=r"(a) : "l"(p));
    return a;
}
__device__ __forceinline__ void cp16(uint32_t s, const void* g) {
    asm volatile("cp.async.cg.shared.global [%0], [%1], 16;\n" ::"r"(s), "l"(g));
}
#define CP_COMMIT() asm volatile("cp.async.commit_group;\n" ::: "memory")
template <int N>
__device__ __forceinline__ void cp_wait() {
    asm volatile("cp.async.wait_group %0;\n" ::"n"(N) : "memory");
}
__device__ __forceinline__ void ldsm4(uint32_t* r, uint32_t a) {
    asm volatile("ldmatrix.sync.aligned.m8n8.x4.shared.b16 {%0,%1,%2,%3}, [%4];"
                 : "=r"(r[0]), "=r"(r[1]), "=r"(r[2]), "=r"(r[3]) : "r"(a));
}
__device__ __forceinline__ void ldsm4t(uint32_t* r, uint32_t a) {
    asm volatile("ldmatrix.sync.aligned.m8n8.x4.trans.shared.b16 {%0,%1,%2,%3}, [%4];"
                 : "=r"(r[0]), "=r"(r[1]), "=r"(r[2]), "=r"(r[3]) : "r"(a));
}
__device__ __forceinline__ void mma16(float* c, const uint32_t* a, const uint32_t* b) {
    asm volatile(
        "mma.sync.aligned.m16n8k16.row.col.f32.f16.f16.f32 "
        "{%0,%1,%2,%3}, {%4,%5,%6,%7}, {%8,%9}, {%0,%1,%2,%3};"
        : "+f"(c[0]), "+f"(c[1]), "+f"(c[2]), "+f"(c[3])
        : "r"(a[0]), "r"(a[1]), "r"(a[2]), "r"(a[3]), "r"(b[0]), "r"(b[1]));
}
__device__ __forceinline__ uint32_t swz128(int r, int c) {  // row = 64 halves
    return (uint32_t)(r * 128 + ((((c >> 3) ^ r) & 7) << 4) + ((c & 7) << 1));
}
__device__ __forceinline__ uint32_t swz512(int r, int c) {  // row = 256 halves
    int g = c >> 3;
    return (uint32_t)(r * 512 + (((g & 24) | ((g ^ r) & 7)) << 4) + ((c & 7) << 1));
}

// ---------------- fp32 -> fp16, 5 arrays in one launch ----------------------
__global__ void f2h5(const float4* __restrict__ s0, const float4* __restrict__ s1,
                     const float4* __restrict__ s2, const float4* __restrict__ s3,
                     const float4* __restrict__ s4,
                     uint4* __restrict__ d0, uint4* __restrict__ d1,
                     uint4* __restrict__ d2, uint4* __restrict__ d3,
                     uint4* __restrict__ d4, int n8) {
    int z = blockIdx.y;
    const float4* s = (z == 0) ? s0 : (z == 1) ? s1 : (z == 2) ? s2 : (z == 3) ? s3 : s4;
    uint4* d = (z == 0) ? d0 : (z == 1) ? d1 : (z == 2) ? d2 : (z == 3) ? d3 : d4;
    int i = blockIdx.x * blockDim.x + threadIdx.x;
    if (i < n8) {
        float4 a = s[2 * i], b = s[2 * i + 1];
        __half2 h0 = __floats2half2_rn(a.x, a.y);
        __half2 h1 = __floats2half2_rn(a.z, a.w);
        __half2 h2 = __floats2half2_rn(b.x, b.y);
        __half2 h3 = __floats2half2_rn(b.z, b.w);
        uint4 o;
        o.x = *reinterpret_cast<uint32_t*>(&h0);
        o.y = *reinterpret_cast<uint32_t*>(&h1);
        o.z = *reinterpret_cast<uint32_t*>(&h2);
        o.w = *reinterpret_cast<uint32_t*>(&h3);
        d[i] = o;
    }
}

#define G_STAGE_B 32768
#define GEMM_SMEM (3 * G_STAGE_B)

// ---- variant A: 8 warps (2x4), warp tile 64x32, 256 threads (for gemm_h) ---
#define GEMM_MAIN_A(Bptr)                                                       \
    float acc[4][4][4];                                                         \
    _Pragma("unroll") for (int i = 0; i < 4; i++)                               \
        _Pragma("unroll") for (int j = 0; j < 4; j++)                           \
            _Pragma("unroll") for (int q = 0; q < 4; q++) acc[i][j][q] = 0.f;   \
    auto loadst = [&](int st, int k0) {                                         \
        uint32_t ab = smb + st * G_STAGE_B, bb = ab + 16384;                    \
        _Pragma("unroll") for (int i = 0; i < 4; i++) {                         \
            int gi = tid + i * 256;                                             \
            int r = gi >> 3, g = gi & 7;                                        \
            uint32_t off = r * 128 + (((g ^ r) & 7) << 4);                      \
            cp16(ab + off, A + (size_t)(m0 + r) * EMBED + k0 + g * 8);          \
            cp16(bb + off, Bptr + (size_t)(n0 + r) * EMBED + k0 + g * 8);       \
        }                                                                       \
    };                                                                          \
    loadst(0, 0); CP_COMMIT();                                                  \
    loadst(1, 64); CP_COMMIT();                                                 \
    int s = 0;                                                                  \
    for (int c = 0; c < 64; c++) {                                              \
        cp_wait<1>();                                                           \
        __syncthreads();                                                        \
        if (c + 2 < 64) loadst((s + 2) % 3, (c + 2) * 64);                      \
        CP_COMMIT();                                                            \
        uint32_t ab = smb + s * G_STAGE_B, bb = ab + 16384;                     \
        _Pragma("unroll") for (int kc = 0; kc < 4; kc++) {                      \
            int kk = kc * 16;                                                   \
            uint32_t af[4][4], bf[2][4];                                        \
            _Pragma("unroll") for (int mi = 0; mi < 4; mi++)                    \
                ldsm4(af[mi], ab + swz128(wm + mi * 16 + a_r, kk + a_c));       \
            _Pragma("unroll") for (int np = 0; np < 2; np++)                    \
                ldsm4(bf[np], bb + swz128(wn + np * 16 + b_r, kk + b_c));       \
            _Pragma("unroll") for (int mi = 0; mi < 4; mi++)                    \
                _Pragma("unroll") for (int ni = 0; ni < 4; ni++)                \
                    mma16(acc[mi][ni], af[mi], &bf[ni >> 1][(ni & 1) * 2]);     \
        }                                                                       \
        if (++s == 3) s = 0;                                                    \
    }

// ---- variant B: 4 warps (2x2), warp tile 64x64, 128 threads (for gemm_qkv) -
#define GEMM_MAIN_B(Bptr)                                                       \
    float acc[4][8][4];                                                         \
    _Pragma("unroll") for (int i = 0; i < 4; i++)                               \
        _Pragma("unroll") for (int j = 0; j < 8; j++)                           \
            _Pragma("unroll") for (int q = 0; q < 4; q++) acc[i][j][q] = 0.f;   \
    auto loadst = [&](int st, int k0) {                                         \
        uint32_t ab = smb + st * G_STAGE_B, bb = ab + 16384;                    \
        _Pragma("unroll") for (int i = 0; i < 8; i++) {                         \
            int gi = tid + i * 128;                                             \
            int r = gi >> 3, g = gi & 7;                                        \
            uint32_t off = r * 128 + (((g ^ r) & 7) << 4);                      \
            cp16(ab + off, A + (size_t)(m0 + r) * EMBED + k0 + g * 8);          \
            cp16(bb + off, Bptr + (size_t)(n0 + r) * EMBED + k0 + g * 8);       \
        }                                                                       \
    };                                                                          \
    loadst(0, 0); CP_COMMIT();                                                  \
    loadst(1, 64); CP_COMMIT();                                                 \
    int s = 0;                                                                  \
    for (int c = 0; c < 64; c++) {                                              \
        cp_wait<1>();                                                           \
        __syncthreads();                                                        \
        if (c + 2 < 64) loadst((s + 2) % 3, (c + 2) * 64);                      \
        CP_COMMIT();                                                            \
        uint32_t ab = smb + s * G_STAGE_B, bb = ab + 16384;                     \
        _Pragma("unroll") for (int kc = 0; kc < 4; kc++) {                      \
            int kk = kc * 16;                                                   \
            uint32_t af[4][4], bf[4][4];                                        \
            _Pragma("unroll") for (int mi = 0; mi < 4; mi++)                    \
                ldsm4(af[mi], ab + swz128(wm + mi * 16 + a_r, kk + a_c));       \
            _Pragma("unroll") for (int np = 0; np < 4; np++)                    \
                ldsm4(bf[np], bb + swz128(wn + np * 16 + b_r, kk + b_c));       \
            _Pragma("unroll") for (int mi = 0; mi < 4; mi++)                    \
                _Pragma("unroll") for (int ni = 0; ni < 8; ni++)                \
                    mma16(acc[mi][ni], af[mi], &bf[ni >> 1][(ni & 1) * 2]);     \
        }                                                                       \
        if (++s == 3) s = 0;                                                    \
    }

// Fused QKV with rotary in epilogue, plain fp16 outputs. grid (32,32,3), 128thr.
__global__ void __launch_bounds__(128, 2) gemm_qkv(const __half* __restrict__ A,
                                                   const __half* __restrict__ Wq,
                                                   const __half* __restrict__ Wk,
                                                   const __half* __restrict__ Wv,
                                                   const int* __restrict__ pid,
                                                   const float* __restrict__ emb,
                                                   __half* __restrict__ Qh,
                                                   __half* __restrict__ Kh,
                                                   __half* __restrict__ Cv) {
    extern __shared__ char smraw[];
    uint32_t smb = smem_u32(smraw);
    int z = blockIdx.z;
    const __half* B = (z == 0) ? Wq : (z == 1) ? Wk : Wv;

    int tid = threadIdx.x;
    int wid = tid >> 5, lane = tid & 31;
    int gid = lane >> 2, tig = lane & 3;
    int wm = (wid >> 1) * 64, wn = (wid & 1) * 64;
    int m0 = blockIdx.y * 128, n0 = blockIdx.x * 128;
    int a_r = lane & 15, a_c = (lane >> 4) << 3;
    int b_r = ((lane >> 4) << 3) + (lane & 7), b_c = ((lane >> 3) & 1) << 3;

    GEMM_MAIN_B(B)

    if (z == 2) {
#pragma unroll
        for (int mi = 0; mi < 4; mi++) {
            int r0 = m0 + wm + mi * 16 + gid;
#pragma unroll
            for (int ni = 0; ni < 8; ni++) {
                int col = n0 + wn + ni * 8 + tig * 2;
                *reinterpret_cast<__half2*>(Cv + (size_t)r0 * EMBED + col) =
                    __floats2half2_rn(acc[mi][ni][0], acc[mi][ni][1]);
                *reinterpret_cast<__half2*>(Cv + (size_t)(r0 + 8) * EMBED + col) =
                    __floats2half2_rn(acc[mi][ni][2], acc[mi][ni][3]);
            }
        }
    } else {
        __half* Hi = (z == 0) ? Qh : Kh;
#pragma unroll
        for (int mi = 0; mi < 4; mi++) {
            int r0 = m0 + wm + mi * 16 + gid;
            int p0 = pid[r0], p1 = pid[r0 + 8];
#pragma unroll
            for (int ni = 0; ni < 8; ni++) {
                int col = n0 + wn + ni * 8 + tig * 2;
                float v0 = acc[mi][ni][0], v1 = acc[mi][ni][1];
                float v2 = acc[mi][ni][2], v3 = acc[mi][ni][3];
                int c = col & 255;
                if (c < 64) {
                    int pr = c >> 1;
                    float sv0 = emb[p0 * 64 + pr], cv0 = emb[p0 * 64 + 32 + pr];
                    float sv1 = emb[p1 * 64 + pr], cv1 = emb[p1 * 64 + 32 + pr];
                    float a0 = v0 * cv0 - v1 * sv0, b0 = v1 * cv0 + v0 * sv0;
                    v0 = a0; v1 = b0;
                    float a1 = v2 * cv1 - v3 * sv1, b1 = v3 * cv1 + v2 * sv1;
                    v2 = a1; v3 = b1;
                }
                size_t o0 = (size_t)r0 * EMBED + col;
                size_t o1 = (size_t)(r0 + 8) * EMBED + col;
                *reinterpret_cast<__half2*>(Hi + o0) = __floats2half2_rn(v0, v1);
                *reinterpret_cast<__half2*>(Hi + o1) = __floats2half2_rn(v2, v3);
            }
        }
    }
}

// Out projection: half in, float out. 256 threads, 8 warps.
__global__ void __launch_bounds__(256, 2) gemm_h(const __half* __restrict__ A,
                                                 const __half* __restrict__ Bw,
                                                 float* __restrict__ C) {
    extern __shared__ char smraw[];
    uint32_t smb = smem_u32(smraw);
    int tid = threadIdx.x;
    int wid = tid >> 5, lane = tid & 31;
    int gid = lane >> 2, tig = lane & 3;
    int wm = (wid >> 2) * 64, wn = (wid & 3) * 32;
    int m0 = blockIdx.y * 128, n0 = blockIdx.x * 128;
    int a_r = lane & 15, a_c = (lane >> 4) << 3;
    int b_r = ((lane >> 4) << 3) + (lane & 7), b_c = ((lane >> 3) & 1) << 3;

    GEMM_MAIN_A(Bw)

#pragma unroll
    for (int mi = 0; mi < 4; mi++) {
        int r0 = m0 + wm + mi * 16 + gid;
#pragma unroll
        for (int ni = 0; ni < 4; ni++) {
            int col = n0 + wn + ni * 8 + tig * 2;
            *reinterpret_cast<float2*>(C + (size_t)r0 * EMBED + col) =
                make_float2(acc[mi][ni][0], acc[mi][ni][1]);
            *reinterpret_cast<float2*>(C + (size_t)(r0 + 8) * EMBED + col) =
                make_float2(acc[mi][ni][2], acc[mi][ni][3]);
        }
    }
}

// ---------------- fp16 HMMA causal flash attention ---------------------------
// BQ=64, BK=32, 4 warps (128 thr), smem 96KB -> 2 CTAs/SM.
// Q fragments held in registers (loaded once); base-2 softmax.
#define FL_SCALE 0.09016844f
#define FL_Q_B 32768
#define FL_KV_ST 32768
#define FL_SMEM (FL_Q_B + 2 * FL_KV_ST)  // 98304

__global__ void __launch_bounds__(128, 2) flash_h(const __half* __restrict__ Qg,
                                                  const __half* __restrict__ Kg,
                                                  const __half* __restrict__ Vg,
                                                  __half* __restrict__ Og) {
    extern __shared__ char smraw[];
    uint32_t smb = smem_u32(smraw);
    const uint32_t QS = smb, KV0 = smb + FL_Q_B;

    int tid = threadIdx.x;
    int wid = tid >> 5, lane = tid & 31;
    int gid = lane >> 2, tig = lane & 3;
    int rw0 = wid * 16;

    int bh = blockIdx.x & 31;
    int qb = 31 - (blockIdx.x >> 5);  // 32 q-blocks of 64; big tiles first
    int b = bh >> 4, h = bh & 15;
    int q0 = qb * 64;
    int nkt = 2 * qb + 2;             // 32-wide k tiles
    size_t tok0 = (size_t)b * NS;

    int a_r = lane & 15, a_c = (lane >> 4) << 3;
    int b_r = ((lane >> 4) << 3) + (lane & 7), b_c = ((lane >> 3) & 1) << 3;

#pragma unroll
    for (int i = 0; i < 16; i++) {  // Q: 64 rows x 256 halves = 2048 cp16
        int gi = tid + i * 128;
        int r = gi >> 5, g = gi & 31;
        uint32_t off = r * 512 + (((g & 24) | ((g ^ r) & 7)) << 4);
        cp16(QS + off, Qg + (tok0 + q0 + r) * EMBED + h * HD + g * 8);
    }
    CP_COMMIT();  // group: Q
    auto loadkv = [&](int st, int kt) {
        uint32_t kb = KV0 + st * FL_KV_ST;
        int k0 = kt * 32;
#pragma unroll
        for (int i = 0; i < 8; i++) {  // 32 rows x 256 halves, K and V
            int gi = tid + i * 128;
            int r = gi >> 5, g = gi & 31;
            uint32_t off = r * 512 + (((g & 24) | ((g ^ r) & 7)) << 4);
            size_t src = (tok0 + k0 + r) * EMBED + h * HD + g * 8;
            cp16(kb + off, Kg + src);
            cp16(kb + 16384 + off, Vg + src);
        }
    };
    loadkv(0, 0);
    CP_COMMIT();  // group: kv0

    // Q resident -> hoist Q fragments into registers (used for all k-tiles)
    cp_wait<1>();
    __syncthreads();
    uint32_t aq[16][4];
#pragma unroll
    for (int kc = 0; kc < 16; kc++)
        ldsm4(aq[kc], QS + swz512(rw0 + a_r, kc * 16 + a_c));

    float o[32][4];
#pragma unroll
    for (int nt = 0; nt < 32; nt++)
#pragma unroll
        for (int q = 0; q < 4; q++) o[nt][q] = 0.f;
    float m0v = -1e30f, m1v = -1e30f, l0v = 0.f, l1v = 0.f;
    int rg0 = q0 + rw0 + gid;

    for (int kt = 0; kt < nkt; kt++) {
        cp_wait<0>();        // stage kt resident
        __syncthreads();     // + all warps done with previous compute
        if (kt + 1 < nkt) loadkv((kt + 1) & 1, kt + 1);
        CP_COMMIT();

        int k0 = kt * 32;
        if (k0 <= q0 + rw0 + 15) {
            uint32_t kb = KV0 + (kt & 1) * FL_KV_ST;
            uint32_t vb = kb + 16384;

            float s4[4][4];
#pragma unroll
            for (int nt = 0; nt < 4; nt++)
#pragma unroll
                for (int q = 0; q < 4; q++) s4[nt][q] = 0.f;

#pragma unroll
            for (int kc = 0; kc < 16; kc++) {
                int kk = kc * 16;
                uint32_t bh4[2][4];
#pragma unroll
                for (int np = 0; np < 2; np++)
                    ldsm4(bh4[np], kb + swz512(np * 16 + b_r, kk + b_c));
#pragma unroll
                for (int np = 0; np < 2; np++) {
                    mma16(s4[2 * np], aq[kc], &bh4[np][0]);
                    mma16(s4[2 * np + 1], aq[kc], &bh4[np][2]);
                }
            }

            bool needmask = (k0 + 31 > q0 + rw0);
#pragma unroll
            for (int nt = 0; nt < 4; nt++) {
#pragma unroll
                for (int q = 0; q < 4; q++) s4[nt][q] *= FL_SCALE;
                if (needmask) {
                    int c0 = k0 + nt * 8 + 2 * tig;
                    if (c0 > rg0) s4[nt][0] = -1e30f;
                    if (c0 + 1 > rg0) s4[nt][1] = -1e30f;
                    if (c0 > rg0 + 8) s4[nt][2] = -1e30f;
                    if (c0 + 1 > rg0 + 8) s4[nt][3] = -1e30f;
                }
            }

            float mx0 = -1e30f, mx1 = -1e30f;
#pragma unroll
            for (int nt = 0; nt < 4; nt++) {
                mx0 = fmaxf(mx0, fmaxf(s4[nt][0], s4[nt][1]));
                mx1 = fmaxf(mx1, fmaxf(s4[nt][2], s4[nt][3]));
            }
            mx0 = fmaxf(mx0, __shfl_xor_sync(0xffffffffu, mx0, 1));
            mx0 = fmaxf(mx0, __shfl_xor_sync(0xffffffffu, mx0, 2));
            mx1 = fmaxf(mx1, __shfl_xor_sync(0xffffffffu, mx1, 1));
            mx1 = fmaxf(mx1, __shfl_xor_sync(0xffffffffu, mx1, 2));
            float mn0 = fmaxf(m0v, mx0), mn1 = fmaxf(m1v, mx1);
            float cor0 = exp2f(m0v - mn0), cor1 = exp2f(m1v - mn1);
            m0v = mn0; m1v = mn1;

            float sum0 = 0.f, sum1 = 0.f;
            uint32_t ph[4][2];
#pragma unroll
            for (int nt = 0; nt < 4; nt++) {
                float p0 = exp2f(s4[nt][0] - mn0);
                float p1 = exp2f(s4[nt][1] - mn0);
                float p2 = exp2f(s4[nt][2] - mn1);
                float p3 = exp2f(s4[nt][3] - mn1);
                sum0 += p0 + p1; sum1 += p2 + p3;
                __half2 h01 = __floats2half2_rn(p0, p1);
                __half2 h23 = __floats2half2_rn(p2, p3);
                ph[nt][0] = *reinterpret_cast<uint32_t*>(&h01);
                ph[nt][1] = *reinterpret_cast<uint32_t*>(&h23);
            }
            sum0 += __shfl_xor_sync(0xffffffffu, sum0, 1);
            sum0 += __shfl_xor_sync(0xffffffffu, sum0, 2);
            sum1 += __shfl_xor_sync(0xffffffffu, sum1, 1);
            sum1 += __shfl_xor_sync(0xffffffffu, sum1, 2);
            l0v = l0v * cor0 + sum0;
            l1v = l1v * cor1 + sum1;

#pragma unroll
            for (int nt = 0; nt < 32; nt++) {
                o[nt][0] *= cor0; o[nt][1] *= cor0;
                o[nt][2] *= cor1; o[nt][3] *= cor1;
            }

#pragma unroll
            for (int kc = 0; kc < 2; kc++) {
                uint32_t a4[4] = {ph[2 * kc][0], ph[2 * kc][1],
                                  ph[2 * kc + 1][0], ph[2 * kc + 1][1]};
#pragma unroll
                for (int dp = 0; dp < 16; dp++) {
                    uint32_t b4[4];
                    ldsm4t(b4, vb + swz512(kc * 16 + a_r, dp * 16 + a_c));
                    mma16(o[2 * dp], a4, &b4[0]);
                    mma16(o[2 * dp + 1], a4, &b4[2]);
                }
            }
        }
    }

    float inv0 = 1.f / l0v, inv1 = 1.f / l1v;
    __half* r0p = Og + (tok0 + rg0) * EMBED + h * HD;
    __half* r1p = Og + (tok0 + rg0 + 8) * EMBED + h * HD;
#pragma unroll
    for (int nt = 0; nt < 32; nt++) {
        int col = nt * 8 + 2 * tig;
        *reinterpret_cast<__half2*>(r0p + col) =
            __floats2half2_rn(o[nt][0] * inv0, o[nt][1] * inv0);
        *reinterpret_cast<__half2*>(r1p + col) =
            __floats2half2_rn(o[nt][2] * inv1, o[nt][3] * inv1);
    }
}

// ---------------------------------------------------------------------------
extern "C" void kernel_launch(void* const* d_in, const int* in_sizes, int n_in,
                              void* d_out, int out_size) {
    const float* hs = (const float*)d_in[0];
    const int* pid = (const int*)d_in[1];
    const float* qw = (const float*)d_in[2];
    const float* kw = (const float*)d_in[3];
    const float* vw = (const float*)d_in[4];
    const float* ow = (const float*)d_in[5];
    const float* emb = (const float*)d_in[6];
    float* out = (float*)d_out;

    __half *hs_h, *wq_h, *wk_h, *wv_h, *wo_h, *qh, *kh, *vh, *att;
    cudaGetSymbolAddress((void**)&hs_h, g_hs_h);
    cudaGetSymbolAddress((void**)&wq_h, g_wq_h);
    cudaGetSymbolAddress((void**)&wk_h, g_wk_h);
    cudaGetSymbolAddress((void**)&wv_h, g_wv_h);
    cudaGetSymbolAddress((void**)&wo_h, g_wo_h);
    cudaGetSymbolAddress((void**)&qh, g_qh);
    cudaGetSymbolAddress((void**)&kh, g_kh);
    cudaGetSymbolAddress((void**)&vh, g_v);
    cudaGetSymbolAddress((void**)&att, g_att);

    cudaFuncSetAttribute(gemm_qkv, cudaFuncAttributeMaxDynamicSharedMemorySize, GEMM_SMEM);
    cudaFuncSetAttribute(gemm_h, cudaFuncAttributeMaxDynamicSharedMemorySize, GEMM_SMEM);
    cudaFuncSetAttribute(flash_h, cudaFuncAttributeMaxDynamicSharedMemorySize, FL_SMEM);

    int n8 = (int)(NELEM / 8);
    f2h5<<<dim3(n8 / 256, 5), 256>>>((const float4*)hs, (const float4*)qw,
                                     (const float4*)kw, (const float4*)vw,
                                     (const float4*)ow, (uint4*)hs_h, (uint4*)wq_h,
                                     (uint4*)wk_h, (uint4*)wv_h, (uint4*)wo_h, n8);

    gemm_qkv<<<dim3(32, 32, 3), 128, GEMM_SMEM>>>(hs_h, wq_h, wk_h, wv_h, pid, emb,
                                                  qh, kh, vh);

    flash_h<<<1024, 128, FL_SMEM>>>(qh, kh, vh, att);

    gemm_h<<<dim3(32, 32), 256, GEMM_SMEM>>>(att, wo_h, out);
}